// round 9
// baseline (speedup 1.0000x reference)
#include <cuda_runtime.h>

// LineSpectralPairsStabilityCheck: (256, 4096, 33) fp32, 1,048,576 rows.
// Per row: keep [0]; 4 passes of {31-step neighbor-separation scan + clip}.
// Plateau at ~6.4 TB/s app bandwidth with phase-convoyed CTAs ->
// cp.async (LDGSTS) double-buffered pipeline: prefetch tile k+1 into the
// alternate smem buffer while computing tile k. Block-wide float4 bursts
// preserved (that's what R7 broke). 4 tiles per CTA.

#define W 33
#define THREADS 128
#define ROWS_PER_TILE 128
#define TILE_ELEMS (ROWS_PER_TILE * W)    // 4224 floats = 16896 B
#define TILE_V4 (TILE_ELEMS / 4)          // 1056 float4
#define TILES_PER_CTA 4

__device__ __forceinline__ void cp_async16(unsigned dst_smem, const void* src) {
    asm volatile("cp.async.cg.shared.global [%0], [%1], 16;"
                 :: "r"(dst_smem), "l"(src));
}
__device__ __forceinline__ void cp_commit() {
    asm volatile("cp.async.commit_group;");
}
template <int N>
__device__ __forceinline__ void cp_wait() {
    asm volatile("cp.async.wait_group %0;" :: "n"(N));
}

__global__ void __launch_bounds__(THREADS)
lsp_stability_kernel(const float* __restrict__ in, float* __restrict__ out)
{
    __shared__ float sm[2][TILE_ELEMS];   // 33792 B

    const int t = threadIdx.x;
    const long long cta_base = (long long)blockIdx.x * TILES_PER_CTA * TILE_ELEMS;

    unsigned sm_u32_base;
    asm("{ .reg .u64 tmp; cvta.to.shared.u64 tmp, %1; cvt.u32.u64 %0, tmp; }"
        : "=r"(sm_u32_base) : "l"((void*)sm));

    const float pi_f  = 3.14159265358979323846f;
    const float min_d = 0.01f * pi_f / 33.0f;   // RATE * pi / (LSP_ORDER + 1)
    const float hi    = pi_f - min_d;

    // ---- prologue: async-fill buffer 0 with tile 0 ----
    {
        const float4* g = (const float4*)(in + cta_base);
        #pragma unroll
        for (int i = t; i < TILE_V4; i += THREADS)
            cp_async16(sm_u32_base + (unsigned)(i * 16), g + i);
        cp_commit();
    }

    #pragma unroll
    for (int k = 0; k < TILES_PER_CTA; k++) {
        const int buf = k & 1;
        const long long tbase = cta_base + (long long)k * TILE_ELEMS;

        // ---- prefetch tile k+1 into the other buffer ----
        if (k + 1 < TILES_PER_CTA) {
            const float4* g = (const float4*)(in + tbase + TILE_ELEMS);
            unsigned dst = sm_u32_base + (unsigned)((buf ^ 1) * TILE_ELEMS * 4);
            #pragma unroll
            for (int i = t; i < TILE_V4; i += THREADS)
                cp_async16(dst + (unsigned)(i * 16), g + i);
            cp_commit();
            cp_wait<1>();    // tile k complete; k+1 still in flight
        } else {
            cp_wait<0>();
        }
        __syncthreads();

        // ---- compute: each thread owns one row (stride-33, conflict-free) ----
        // Channel 0 (K) passes through smem untouched.
        float* buf_f = sm[buf];
        const int rbase = t * W;
        float v[W];   // v[0] unused
        #pragma unroll
        for (int i = 1; i < W; i++)
            v[i] = buf_f[rbase + i];

        #pragma unroll
        for (int it = 0; it < 4; it++) {
            // chain: u = c + m (FADD) -> s = max(u,0) (FMNMX)
            //     -> c = fma(s,0.5,nxt) (FFMA); rest off-chain.
            float c = v[1];
            #pragma unroll
            for (int i = 2; i <= 32; i++) {
                float nxt = v[i];
                float m = min_d - nxt;            // off-chain
                float u = c + m;                  // chain
                float s = fmaxf(u, 0.0f);         // chain
                float o = fmaf(s, -0.5f, c);      // off-chain output
                o = fmaxf(o, min_d);
                v[i - 1] = fminf(o, hi);
                c = fmaf(s, 0.5f, nxt);           // chain (carried unclipped)
            }
            v[32] = fminf(fmaxf(c, min_d), hi);
        }

        #pragma unroll
        for (int i = 1; i < W; i++)
            buf_f[rbase + i] = v[i];
        __syncthreads();

        // ---- destage: coalesced streaming store of the whole tile ----
        float4* g_out = (float4*)(out + tbase);
        const float4* s4 = (const float4*)buf_f;
        #pragma unroll
        for (int i = t; i < TILE_V4; i += THREADS)
            __stcs(&g_out[i], s4[i]);

        // protect this buffer from next iteration's prefetch (tile k+2)
        __syncthreads();
    }
}

extern "C" void kernel_launch(void* const* d_in, const int* in_sizes, int n_in,
                              void* d_out, int out_size)
{
    const float* in = (const float*)d_in[0];
    float* out = (float*)d_out;

    const int total = in_sizes[0];                     // 256*4096*33
    const int rows = total / W;                        // 1,048,576
    const int tiles = rows / ROWS_PER_TILE;            // 8192
    const int blocks = tiles / TILES_PER_CTA;          // 2048 (exact)

    lsp_stability_kernel<<<blocks, THREADS>>>(in, out);
}

// round 10
// speedup vs baseline: 1.3923x; 1.3923x over previous
#include <cuda_runtime.h>

// LineSpectralPairsStabilityCheck: (256, 4096, 33) fp32, 1,048,576 rows.
// Per row: keep [0]; 4 passes of {31-step neighbor-separation scan + clip}.
// R5 shape (1 row/thread, 44 regs, block-staged float4 streaming bursts) but
// with 64-thread CTAs: ~2x more independently-phased CTAs per SM so the
// per-CTA load/compute/store phases superpose into a smoother DRAM demand.

#define W 33
#define THREADS 64
#define ROWS_PER_BLOCK 64
#define TILE_ELEMS (ROWS_PER_BLOCK * W)   // 2112 floats = 8448 B
#define TILE_VEC4 (TILE_ELEMS / 4)        // 528

__global__ void __launch_bounds__(THREADS)
lsp_stability_kernel(const float* __restrict__ in, float* __restrict__ out)
{
    __shared__ float sm[TILE_ELEMS];

    const int t = threadIdx.x;
    const long long base = (long long)blockIdx.x * TILE_ELEMS;

    // ---- coalesced vectorized streaming load of the block tile ----
    const float4* __restrict__ in4 = (const float4*)(in + base);
    float4* sm4 = (float4*)sm;
    #pragma unroll
    for (int i = t; i < TILE_VEC4; i += THREADS)
        sm4[i] = __ldcs(&in4[i]);
    __syncthreads();

    // ---- each thread owns one row (stride-33 smem: conflict-free) ----
    // Channel 0 (K) passes through smem untouched.
    const int rbase = t * W;
    float v[W];   // v[0] unused
    #pragma unroll
    for (int i = 1; i < W; i++)
        v[i] = sm[rbase + i];

    const float pi_f  = 3.14159265358979323846f;
    const float min_d = 0.01f * pi_f / 33.0f;   // RATE * pi / (LSP_ORDER + 1)
    const float hi    = pi_f - min_d;

    #pragma unroll
    for (int it = 0; it < 4; it++) {
        // chain per step: u = c + m (FADD) -> s = max(u,0) (FMNMX)
        //              -> c = fma(s, 0.5, nxt) (FFMA); rest off-chain.
        float c = v[1];
        #pragma unroll
        for (int i = 2; i <= 32; i++) {
            float nxt = v[i];
            float m = min_d - nxt;            // off-chain
            float u = c + m;                  // chain
            float s = fmaxf(u, 0.0f);         // chain
            float o = fmaf(s, -0.5f, c);      // off-chain output
            o = fmaxf(o, min_d);
            v[i - 1] = fminf(o, hi);
            c = fmaf(s, 0.5f, nxt);           // chain (carried unclipped)
        }
        v[32] = fminf(fmaxf(c, min_d), hi);
    }

    // ---- write row back to private smem region ----
    #pragma unroll
    for (int i = 1; i < W; i++)
        sm[rbase + i] = v[i];
    __syncthreads();

    // ---- coalesced vectorized streaming store ----
    float4* __restrict__ out4 = (float4*)(out + base);
    #pragma unroll
    for (int i = t; i < TILE_VEC4; i += THREADS)
        __stcs(&out4[i], sm4[i]);
}

extern "C" void kernel_launch(void* const* d_in, const int* in_sizes, int n_in,
                              void* d_out, int out_size)
{
    const float* in = (const float*)d_in[0];
    float* out = (float*)d_out;

    const int total = in_sizes[0];            // 256*4096*33 = 34,603,008
    const int rows = total / W;               // 1,048,576
    const int blocks = rows / ROWS_PER_BLOCK; // 16384 (exact)

    lsp_stability_kernel<<<blocks, THREADS>>>(in, out);
}

// round 12
// speedup vs baseline: 1.6810x; 1.2073x over previous
#include <cuda_runtime.h>
#include <cstdint>

// LineSpectralPairsStabilityCheck: (256, 4096, 33) fp32, 1,048,576 rows.
// Per row: keep [0]; 4 passes of {31-step neighbor-separation scan + clip}.
// R5 compute shape (1 row/thread, 128-thread CTA, conflict-free stride-33
// smem) but global<->shared staging via cp.async.bulk (TMA bulk copy):
// one 16896B engine copy in, one out — removes ~20% of the instruction
// stream and decouples DRAM burst density from warp scheduling.

#define W 33
#define THREADS 128
#define ROWS_PER_BLOCK 128
#define TILE_ELEMS (ROWS_PER_BLOCK * W)   // 4224 floats
#define TILE_BYTES (TILE_ELEMS * 4)       // 16896 B (16B-multiple)

__global__ void __launch_bounds__(THREADS)
lsp_stability_kernel(const float* __restrict__ in, float* __restrict__ out)
{
    __shared__ alignas(128) float sm[TILE_ELEMS];
    __shared__ alignas(8) unsigned long long mbar;

    const int t = threadIdx.x;
    const long long base = (long long)blockIdx.x * TILE_ELEMS;

    uint32_t sm_addr, mbar_addr;
    asm("{ .reg .u64 u; cvta.to.shared.u64 u, %1; cvt.u32.u64 %0, u; }"
        : "=r"(sm_addr) : "l"((void*)sm));
    asm("{ .reg .u64 u; cvta.to.shared.u64 u, %1; cvt.u32.u64 %0, u; }"
        : "=r"(mbar_addr) : "l"((void*)&mbar));

    // ---- init mbarrier, then one bulk G->S copy of the whole tile ----
    if (t == 0) {
        asm volatile("mbarrier.init.shared.b64 [%0], 1;" :: "r"(mbar_addr) : "memory");
    }
    __syncthreads();
    if (t == 0) {
        asm volatile("mbarrier.arrive.expect_tx.shared.b64 _, [%0], %1;"
                     :: "r"(mbar_addr), "r"((uint32_t)TILE_BYTES) : "memory");
        asm volatile("cp.async.bulk.shared::cta.global.mbarrier::complete_tx::bytes "
                     "[%0], [%1], %2, [%3];"
                     :: "r"(sm_addr), "l"(in + base), "r"((uint32_t)TILE_BYTES),
                        "r"(mbar_addr) : "memory");
    }
    // ---- wait for the tile (parity 0; one-shot per CTA) ----
    asm volatile(
        "{\n\t"
        ".reg .pred P1;\n\t"
        "WAIT_LOOP_%=:\n\t"
        "mbarrier.try_wait.parity.acquire.cta.shared::cta.b64 P1, [%0], 0, 0x989680;\n\t"
        "@P1 bra.uni WAIT_DONE_%=;\n\t"
        "bra.uni WAIT_LOOP_%=;\n\t"
        "WAIT_DONE_%=:\n\t"
        "}"
        :: "r"(mbar_addr) : "memory");

    // ---- each thread owns one row (stride-33 smem: conflict-free) ----
    // Channel 0 (K) passes through smem untouched.
    const int rbase = t * W;
    float v[W];   // v[0] unused
    #pragma unroll
    for (int i = 1; i < W; i++)
        v[i] = sm[rbase + i];

    const float pi_f  = 3.14159265358979323846f;
    const float min_d = 0.01f * pi_f / 33.0f;   // RATE * pi / (LSP_ORDER + 1)
    const float hi    = pi_f - min_d;

    #pragma unroll
    for (int it = 0; it < 4; it++) {
        // chain per step: u = c + m (FADD) -> s = max(u,0) (FMNMX)
        //              -> c = fma(s, 0.5, nxt) (FFMA); rest off-chain.
        float c = v[1];
        #pragma unroll
        for (int i = 2; i <= 32; i++) {
            float nxt = v[i];
            float m = min_d - nxt;            // off-chain
            float u = c + m;                  // chain
            float s = fmaxf(u, 0.0f);         // chain
            float o = fmaf(s, -0.5f, c);      // off-chain output
            o = fmaxf(o, min_d);
            v[i - 1] = fminf(o, hi);
            c = fmaf(s, 0.5f, nxt);           // chain (carried unclipped)
        }
        v[32] = fminf(fmaxf(c, min_d), hi);
    }

    // ---- write row back to its private smem region ----
    #pragma unroll
    for (int i = 1; i < W; i++)
        sm[rbase + i] = v[i];
    __syncthreads();

    // ---- one bulk S->G copy of the whole tile ----
    if (t == 0) {
        asm volatile("fence.proxy.async.shared::cta;" ::: "memory");
        asm volatile("cp.async.bulk.global.shared::cta.bulk_group [%0], [%1], %2;"
                     :: "l"(out + base), "r"(sm_addr), "r"((uint32_t)TILE_BYTES)
                     : "memory");
        asm volatile("cp.async.bulk.commit_group;" ::: "memory");
        asm volatile("cp.async.bulk.wait_group 0;" ::: "memory");
    }
}

extern "C" void kernel_launch(void* const* d_in, const int* in_sizes, int n_in,
                              void* d_out, int out_size)
{
    const float* in = (const float*)d_in[0];
    float* out = (float*)d_out;

    const int total = in_sizes[0];            // 256*4096*33 = 34,603,008
    const int rows = total / W;               // 1,048,576
    const int blocks = rows / ROWS_PER_BLOCK; // 8192 (exact)

    lsp_stability_kernel<<<blocks, THREADS>>>(in, out);
}